// round 1
// baseline (speedup 1.0000x reference)
#include <cuda_runtime.h>

#define HH 128
#define WW 128
#define CC 16
#define FF 16
#define NB 2
#define SNX 32
#define SNY 32
#define PIX_STRIDE 260   // 256 + 4 pad: float4 lanes stride 260 words -> conflict-free

// Parity scratch: [4][B][H][W][C] floats = 8 MB. Every element written exactly once
// per launch (same-parity patches tile the wrapped image disjointly).
__device__ float g_scratch[4ull * NB * HH * WW * CC];

// smem layout (floats): bs[64*260] | pet_s[64*16] | ratio_s[256] | Ks[16*65]
#define SMEM_FLOATS (64 * PIX_STRIDE + 64 * 16 + 256 + 16 * 65)
#define SMEM_BYTES (SMEM_FLOATS * 4)

__global__ __launch_bounds__(256) void patch_filter_kernel(
    const float* __restrict__ pet, const float* __restrict__ bfeat)
{
    extern __shared__ float sm[];
    float* bs      = sm;
    float* pet_s   = sm + 64 * PIX_STRIDE;
    float* ratio_s = pet_s + 64 * 16;
    float* Ks      = ratio_s + 256;

    const int sny = blockIdx.x;
    const int snx = blockIdx.y;
    const int bz  = blockIdx.z;
    const int t   = threadIdx.x;

    const int r0 = snx * 4 - 2;   // SAME pad = 2
    const int c0 = sny * 4 - 2;

    // ---- Stage b patch (8x8 pixels x 256 floats), zero-fill out of range ----
    for (int idx = t; idx < 64 * 64; idx += 256) {
        int pix = idx >> 6;          // 0..63
        int q   = idx & 63;          // float4 index within pixel (256 floats)
        int u = pix >> 3, v = pix & 7;
        int r = r0 + u, col = c0 + v;
        float4 val = make_float4(0.f, 0.f, 0.f, 0.f);
        if ((unsigned)r < HH && (unsigned)col < WW) {
            val = *(const float4*)(bfeat + ((bz * HH + r) * WW + col) * (CC * FF) + q * 4);
        }
        *(float4*)(bs + pix * PIX_STRIDE + q * 4) = val;
    }
    // ---- Stage pet patch (8x8 x 16 floats) ----
    {
        int pix = t >> 2;            // 64 pixels, 4 float4 each -> exactly 256 threads
        int q   = t & 3;
        int u = pix >> 3, v = pix & 7;
        int r = r0 + u, col = c0 + v;
        float4 val = make_float4(0.f, 0.f, 0.f, 0.f);
        if ((unsigned)r < HH && (unsigned)col < WW) {
            val = *(const float4*)(pet + ((bz * HH + r) * WW + col) * CC + q * 4);
        }
        *(float4*)(pet_s + pix * 16 + q * 4) = val;
    }
    __syncthreads();

    // ---- Pass 1: per (c,f) reductions over the 64 patch pixels ----
    {
        const int c = t >> 4;        // thread t <-> within-pixel offset c*16+f
        float diag = 0.f, kp = 0.f;
#pragma unroll 8
        for (int pix = 0; pix < 64; pix++) {
            float bv = bs[pix * PIX_STRIDE + t];
            float pv = pet_s[pix * 16 + c];
            diag += bv;
            kp   += pv * bv;
        }
        ratio_s[t] = (diag != 0.f) ? (kp / diag) : 0.f;   // divide_no_nan
    }
    __syncthreads();

    // ---- Pass 2: K[pix,c] = sum_f ratio[c,f] * b[pix,c,f] ----
#pragma unroll
    for (int k = 0; k < 4; k++) {
        int task = k * 256 + t;      // 1024 tasks = 64 pix x 16 c
        int pix  = task & 63;
        int cc   = task >> 6;
        const float4* bp = (const float4*)(bs + pix * PIX_STRIDE + cc * 16);
        const float4* rp = (const float4*)(ratio_s + cc * 16);   // warp-broadcast
        float acc = 0.f;
#pragma unroll
        for (int q = 0; q < 4; q++) {
            float4 bv = bp[q];
            float4 rv = rp[q];
            acc += bv.x * rv.x + bv.y * rv.y + bv.z * rv.z + bv.w * rv.w;
        }
        Ks[cc * 65 + pix] = acc;     // 65 pad -> write conflict-free
    }
    __syncthreads();

    // ---- Scatter to parity scratch at wrapped coordinates (no atomics) ----
    const int kpar = (snx & 1) + 2 * (sny & 1);
    float* dstbase = g_scratch + ((size_t)(kpar * NB + bz)) * HH * WW * CC;
    for (int idx = t; idx < 1024; idx += 256) {
        int pix = idx >> 4, cc = idx & 15;
        int u = pix >> 3, v = pix & 7;
        int r   = (r0 + u) & (HH - 1);   // -2 & 127 = 126, 129 & 127 = 1 (wrap = roll)
        int col = (c0 + v) & (WW - 1);
        dstbase[(r * WW + col) * CC + cc] = Ks[cc * 65 + pix];
    }
}

__global__ __launch_bounds__(256) void combine_kernel(float* __restrict__ out)
{
    int gid = blockIdx.x * blockDim.x + threadIdx.x;   // 131072 float4s
    const size_t stride4 = (size_t)NB * HH * WW * CC / 4;
    const float4* s = (const float4*)g_scratch;
    float4 a = s[gid];
    float4 b = s[gid + stride4];
    float4 c = s[gid + 2 * stride4];
    float4 d = s[gid + 3 * stride4];
    float4 r;
    r.x = 0.25f * (a.x + b.x + c.x + d.x);
    r.y = 0.25f * (a.y + b.y + c.y + d.y);
    r.z = 0.25f * (a.z + b.z + c.z + d.z);
    r.w = 0.25f * (a.w + b.w + c.w + d.w);
    ((float4*)out)[gid] = r;
}

extern "C" void kernel_launch(void* const* d_in, const int* in_sizes, int n_in,
                              void* d_out, int out_size)
{
    // Input order per reference signature: mr (unused), pet, b, px, py, sx, sy
    const float* pet   = (const float*)d_in[1];
    const float* bfeat = (const float*)d_in[2];

    cudaFuncSetAttribute(patch_filter_kernel,
                         cudaFuncAttributeMaxDynamicSharedMemorySize, SMEM_BYTES);

    dim3 grid(SNY, SNX, NB);
    patch_filter_kernel<<<grid, 256, SMEM_BYTES>>>(pet, bfeat);

    // out_size = 2*128*128*16 = 524288 floats = 131072 float4s
    combine_kernel<<<(NB * HH * WW * CC / 4) / 256, 256>>>((float*)d_out);
}

// round 2
// speedup vs baseline: 1.6772x; 1.6772x over previous
#include <cuda_runtime.h>

#define HH 128
#define WW 128
#define CC 16
#define FF 16
#define NB 2
#define SNX 32
#define SNY 32

// Parity scratch: [4][B][H][W][C] floats = 8 MB. Every element written exactly once.
__device__ float g_scratch[4ull * NB * HH * WW * CC];

__global__ __launch_bounds__(256) void patch_filter_kernel(
    const float* __restrict__ pet, const float* __restrict__ bfeat)
{
    __shared__ float pet_s[64 * 16];     // 4 KB
    __shared__ float part_d[4 * 256];    // 4 KB  cross-g diag partials
    __shared__ float part_k[4 * 256];    // 4 KB  cross-g kp partials
    __shared__ float ratio_s[256];       // 1 KB

    const int sny = blockIdx.x;
    const int snx = blockIdx.y;
    const int bz  = blockIdx.z;
    const int t   = threadIdx.x;
    const int q   = t & 63;              // float4 slot within pixel (0..63)
    const int g   = t >> 6;              // pixel-group: owns pix == g (mod 4)
    const int c   = q >> 2;              // channel this q-slot belongs to

    const int r0 = snx * 4 - 2;          // SAME pad = 2
    const int c0 = sny * 4 - 2;

    // ---- Stage pet patch (8x8 x 16 floats) ----
    {
        int pix = t >> 2, qq = t & 3;
        int r = r0 + (pix >> 3), col = c0 + (pix & 7);
        float4 v = make_float4(0.f, 0.f, 0.f, 0.f);
        if ((unsigned)r < HH && (unsigned)col < WW)
            v = *(const float4*)(pet + ((bz * HH + r) * WW + col) * CC + qq * 4);
        *(float4*)(pet_s + pix * 16 + qq * 4) = v;
    }
    __syncthreads();

    // ---- Load b into registers, fuse pass-1 partial reductions ----
    float4 b4[16];
    float4 dsum = make_float4(0.f, 0.f, 0.f, 0.f);
    float4 ksum = make_float4(0.f, 0.f, 0.f, 0.f);
    const float* bbase = bfeat + (size_t)bz * HH * WW * CC * FF + q * 4;
#pragma unroll
    for (int k = 0; k < 16; k++) {
        int pix = 4 * k + g;
        int r = r0 + (pix >> 3), col = c0 + (pix & 7);
        float4 bv = make_float4(0.f, 0.f, 0.f, 0.f);
        if ((unsigned)r < HH && (unsigned)col < WW)
            bv = *(const float4*)(bbase + (r * WW + col) * (CC * FF));
        b4[k] = bv;
        float pv = pet_s[pix * 16 + c];   // broadcast-friendly
        dsum.x += bv.x; dsum.y += bv.y; dsum.z += bv.z; dsum.w += bv.w;
        ksum.x = fmaf(pv, bv.x, ksum.x);
        ksum.y = fmaf(pv, bv.y, ksum.y);
        ksum.z = fmaf(pv, bv.z, ksum.z);
        ksum.w = fmaf(pv, bv.w, ksum.w);
    }
    *(float4*)(part_d + g * 256 + q * 4) = dsum;
    *(float4*)(part_k + g * 256 + q * 4) = ksum;
    __syncthreads();

    // ---- ratio[cf] = divide_no_nan(kp, diag), thread t handles cf = t ----
    {
        float d  = part_d[t] + part_d[256 + t] + part_d[512 + t] + part_d[768 + t];
        float kk = part_k[t] + part_k[256 + t] + part_k[512 + t] + part_k[768 + t];
        ratio_s[t] = (d != 0.f) ? (kk / d) : 0.f;
    }
    __syncthreads();

    const float4 rat = *(const float4*)(ratio_s + q * 4);

    // ---- Pass 2 + scatter: K[pix,c] via 4-lane shfl reduction ----
    const int kpar = (snx & 1) + 2 * (sny & 1);
    float* dst = g_scratch + ((size_t)(kpar * NB + bz)) * HH * WW * CC;
    const bool lead = ((q & 3) == 0);
#pragma unroll
    for (int k = 0; k < 16; k++) {
        float4 bv = b4[k];
        float Kp = bv.x * rat.x + bv.y * rat.y + bv.z * rat.z + bv.w * rat.w;
        Kp += __shfl_xor_sync(0xffffffffu, Kp, 1);
        Kp += __shfl_xor_sync(0xffffffffu, Kp, 2);
        if (lead) {
            int pix = 4 * k + g;
            int r   = (r0 + (pix >> 3)) & (HH - 1);   // wrap == jnp.roll
            int col = (c0 + (pix & 7)) & (WW - 1);
            dst[(r * WW + col) * CC + c] = Kp;
        }
    }
}

__global__ __launch_bounds__(256) void combine_kernel(float* __restrict__ out)
{
    const size_t s4 = (size_t)NB * HH * WW * CC / 4;
    const float4* s = (const float4*)g_scratch;
    int base = (blockIdx.x * 256 + threadIdx.x) * 2;   // 2 float4 per thread -> MLP 8
    float4 a0 = s[base],              a1 = s[base + 1];
    float4 b0 = s[base + s4],         b1 = s[base + 1 + s4];
    float4 c0 = s[base + 2 * s4],     c1 = s[base + 1 + 2 * s4];
    float4 d0 = s[base + 3 * s4],     d1 = s[base + 1 + 3 * s4];
    float4 r0, r1;
    r0.x = 0.25f * (a0.x + b0.x + c0.x + d0.x);
    r0.y = 0.25f * (a0.y + b0.y + c0.y + d0.y);
    r0.z = 0.25f * (a0.z + b0.z + c0.z + d0.z);
    r0.w = 0.25f * (a0.w + b0.w + c0.w + d0.w);
    r1.x = 0.25f * (a1.x + b1.x + c1.x + d1.x);
    r1.y = 0.25f * (a1.y + b1.y + c1.y + d1.y);
    r1.z = 0.25f * (a1.z + b1.z + c1.z + d1.z);
    r1.w = 0.25f * (a1.w + b1.w + c1.w + d1.w);
    ((float4*)out)[base]     = r0;
    ((float4*)out)[base + 1] = r1;
}

extern "C" void kernel_launch(void* const* d_in, const int* in_sizes, int n_in,
                              void* d_out, int out_size)
{
    // Input order per reference signature: mr (unused), pet, b, px, py, sx, sy
    const float* pet   = (const float*)d_in[1];
    const float* bfeat = (const float*)d_in[2];

    dim3 grid(SNY, SNX, NB);
    patch_filter_kernel<<<grid, 256>>>(pet, bfeat);

    // out_size = 2*128*128*16 = 524288 floats = 131072 float4s, 2 per thread
    combine_kernel<<<(NB * HH * WW * CC / 4) / 512, 256>>>((float*)d_out);
}